// round 15
// baseline (speedup 1.0000x reference)
#include <cuda_runtime.h>
#include <math.h>
#include <complex>

typedef unsigned long long ull;

// ---------------------------------------------------------------- host CG ---
struct CGPack { float c[363]; };
#define O000 0
#define O011 1
#define O022 10
#define O101 35
#define O110 44
#define O112 53
#define O121 98
#define O202 143
#define O211 168
#define O220 213
#define O222 238

static double fct(int n) { double r = 1.0; for (int i = 2; i <= n; ++i) r *= i; return r; }

static double su2cg(int j1, int m1, int j2, int m2, int j3, int m3) {
    if (m3 != m1 + m2) return 0.0;
    int vmin = -j1 + j2 + m3; if (-j1 + m1 > vmin) vmin = -j1 + m1; if (0 > vmin) vmin = 0;
    int vmax = j2 + j3 + m1; if (j3 - j1 + j2 < vmax) vmax = j3 - j1 + j2; if (j3 + m3 < vmax) vmax = j3 + m3;
    if (vmax < vmin) return 0.0;
    double C = sqrt((2 * j3 + 1) * fct(j3 + j1 - j2) * fct(j3 - j1 + j2) * fct(j1 + j2 - j3)
                    * fct(j3 + m3) * fct(j3 - m3)
                    / (fct(j1 + j2 + j3 + 1) * fct(j1 - m1) * fct(j1 + m1) * fct(j2 - m2) * fct(j2 + m2)));
    double S = 0.0;
    for (int v = vmin; v <= vmax; ++v) {
        double sgn = ((v + j2 + m2) & 1) ? -1.0 : 1.0;
        S += sgn * fct(j2 + j3 + m1 - v) * fct(j1 - m1 + v)
             / (fct(v) * fct(j3 - j1 + j2 - v) * fct(j3 + m3 - v) * fct(v + j1 - j2 - m3));
    }
    return C * S;
}

typedef std::complex<double> cplx;

static void qmat(int l, cplx* q) {
    int n = 2 * l + 1;
    for (int i = 0; i < n * n; ++i) q[i] = 0.0;
    const double is2 = 1.0 / sqrt(2.0);
    for (int m = -l; m < 0; ++m) {
        q[(l + m) * n + (l - m)] = is2;
        q[(l + m) * n + (l + m)] = cplx(0.0, -is2);
    }
    q[l * n + l] = 1.0;
    for (int m = 1; m <= l; ++m) {
        double s = (m & 1) ? -1.0 : 1.0;
        q[(l + m) * n + (l + m)] = s * is2;
        q[(l + m) * n + (l - m)] = cplx(0.0, s * is2);
    }
    cplx ph = 1.0; for (int i = 0; i < l; ++i) ph *= cplx(0.0, -1.0);
    for (int i = 0; i < n * n; ++i) q[i] *= ph;
}

static void real_cg(int l1, int l2, int l3, float* out, double scale) {
    int n1 = 2 * l1 + 1, n2 = 2 * l2 + 1, n3 = 2 * l3 + 1;
    cplx Q1[25], Q2[25], Q3[25];
    qmat(l1, Q1); qmat(l2, Q2); qmat(l3, Q3);
    for (int j = 0; j < n1; ++j)
        for (int lc = 0; lc < n2; ++lc)
            for (int mm = 0; mm < n3; ++mm) {
                cplx s = 0.0;
                for (int i = 0; i < n1; ++i)
                    for (int kk = 0; kk < n2; ++kk) {
                        int m1 = i - l1, m2 = kk - l2, m3 = m1 + m2;
                        if (m3 < -l3 || m3 > l3) continue;
                        double cg = su2cg(l1, m1, l2, m2, l3, m3);
                        if (cg == 0.0) continue;
                        s += Q1[i * n1 + j] * Q2[kk * n2 + lc] * std::conj(Q3[(l3 + m3) * n3 + mm]) * cg;
                    }
                out[(j * n2 + lc) * n3 + mm] = (float)(s.real() * scale);
            }
}

static void build_cg(CGPack& cg) {
    double fan0 = 64.0 * 64 + 32.0 * 32 + 16.0 * 16;
    double fan1 = 64.0 * 32 + 32.0 * 64 + 32.0 * 16 + 16.0 * 32;
    double fan2 = 64.0 * 16 + 16.0 * 64 + 32.0 * 32 + 16.0 * 16;
    double s0 = 1.0 / sqrt(fan0);
    double s1 = sqrt(3.0) / sqrt(fan1);
    double s2 = sqrt(5.0) / sqrt(fan2);
    real_cg(0, 0, 0, cg.c + O000, s0);
    real_cg(0, 1, 1, cg.c + O011, s1);
    real_cg(0, 2, 2, cg.c + O022, s2);
    real_cg(1, 0, 1, cg.c + O101, s1);
    real_cg(1, 1, 0, cg.c + O110, s0);
    real_cg(1, 1, 2, cg.c + O112, s2);
    real_cg(1, 2, 1, cg.c + O121, s1);
    real_cg(2, 0, 2, cg.c + O202, s2);
    real_cg(2, 1, 1, cg.c + O211, s1);
    real_cg(2, 2, 0, cg.c + O220, s0);
    real_cg(2, 2, 2, cg.c + O222, s2);
}

// --------------------------------------------------- packed merged weights --
// Slice-major DUPLICATED layout: G[slice][feature][8 cols x 2 (dup)].
// Each 8-col unit streams contiguous 64B/feature; every weight stored (w,w)
// so one f32x2 FMA covers both rows. +1024 floats pad for cp.async overrun.
#define NF0 2744
#define NF1 2560
#define NF2 1688
#define NG0 (NF0 * 64)
#define NG1 (NF1 * 32)
#define NG2 (NF2 * 16)
__device__ __align__(16) float g_G0[NG0 * 2 + 1024];
__device__ __align__(16) float g_G1[NG1 * 2 + 1024];
__device__ __align__(16) float g_G2[NG2 * 2 + 1024];

__global__ void prep_all(const float* __restrict__ W0, const float* __restrict__ W1,
                         const float* __restrict__ W2, const float* __restrict__ W3,
                         const float* __restrict__ W4, const float* __restrict__ W5,
                         const float* __restrict__ W6, const float* __restrict__ W7,
                         const float* __restrict__ W8, const float* __restrict__ W9,
                         const float* __restrict__ W10, float c000) {
    int i = blockIdx.x * blockDim.x + threadIdx.x;
    if (i < NG0) {
        int f = i >> 6, w = i & 63;
        float val;
        if (f < 2080) {
            int t = f, u = 0; while (t >= 64 - u) { t -= 64 - u; ++u; } int v = u + t;
            val = W0[(u * 64 + v) * 64 + w];
            if (v != u) val += W0[(v * 64 + u) * 64 + w];
            val *= c000;   // fold scalar CG of the 0x0->0 path
        } else if (f < 2608) {
            int t = f - 2080, u = 0; while (t >= 32 - u) { t -= 32 - u; ++u; } int v = u + t;
            val = W4[(u * 32 + v) * 64 + w];
            if (v != u) val += W4[(v * 32 + u) * 64 + w];
        } else {
            int t = f - 2608, u = 0; while (t >= 16 - u) { t -= 16 - u; ++u; } int v = u + t;
            val = W9[(u * 16 + v) * 64 + w];
            if (v != u) val += W9[(v * 16 + u) * 64 + w];
        }
        int o = (w >> 3) * (NF0 * 16) + f * 16 + (w & 7) * 2;
        g_G0[o] = val; g_G0[o + 1] = val;
        return;
    }
    i -= NG0;
    if (i < NG1) {
        int f = i >> 5, w = i & 31;
        float val;
        if (f < 2048) {              // outer v1 (32) x inner u0 (64)
            int v = f >> 6, u = f & 63;
            val = W1[(u * 32 + v) * 32 + w] + W3[(v * 64 + u) * 32 + w];
        } else {                     // outer v2 (16) x inner u1 (32)
            int t = f - 2048; int v = t >> 5, u = t & 31;
            val = W6[(u * 16 + v) * 32 + w] + W8[(v * 32 + u) * 32 + w];
        }
        int o = (w >> 3) * (NF1 * 16) + f * 16 + (w & 7) * 2;
        g_G1[o] = val; g_G1[o + 1] = val;
        return;
    }
    i -= NG1;
    if (i < NG2) {
        int f = i >> 4, w = i & 15;
        float val;
        if (f < 1024) {              // outer v2 (16) x inner u0 (64)
            int v = f >> 6, u = f & 63;
            val = W2[(u * 16 + v) * 16 + w] + W7[(v * 64 + u) * 16 + w];
        } else if (f < 1552) {
            int t = f - 1024, u = 0; while (t >= 32 - u) { t -= 32 - u; ++u; } int v = u + t;
            val = W5[(u * 32 + v) * 16 + w];
            if (v != u) val += W5[(v * 32 + u) * 16 + w];
        } else {
            int t = f - 1552, u = 0; while (t >= 16 - u) { t -= 16 - u; ++u; } int v = u + t;
            val = W10[(u * 16 + v) * 16 + w];
            if (v != u) val += W10[(v * 16 + u) * 16 + w];
        }
        int o = (w >> 3) * (NF2 * 16) + f * 16 + (w & 7) * 2;
        g_G2[o] = val; g_G2[o + 1] = val;
    }
}

// -------------------------------------------------------------- f32x2 ops ---
__device__ __forceinline__ ull fma2(ull a, ull b, ull c) {
    ull d; asm("fma.rn.f32x2 %0, %1, %2, %3;" : "=l"(d) : "l"(a), "l"(b), "l"(c)); return d;
}
__device__ __forceinline__ ull mul2(ull a, ull b) {
    ull d; asm("mul.rn.f32x2 %0, %1, %2;" : "=l"(d) : "l"(a), "l"(b)); return d;
}
__device__ __forceinline__ ull bc2(float s) {
    ull d; asm("mov.b64 %0, {%1, %1};" : "=l"(d) : "f"(s)); return d;
}
__device__ __forceinline__ ull ld2(const float* p) { return *reinterpret_cast<const ull*>(p); }

// ----------------------------------------------- cp.async weight cursor -----
// Warp-private double buffer: 2 x (16 features x 64B) = 2 x 1KB in smem.
// Each lane copies 2 x 16B per chunk. Prefetch distance = 16 iterations.
struct WCur {
    const float* g;   // next chunk global ptr
    float*       s;   // generic smem base (512 floats)
    unsigned     sb;  // shared-space byte address of s
    int          idx;
    int          phase;
    int          lane;
};

__device__ __forceinline__ void wc_init(WCur& c, const float* gslice, float* sreg, int lane) {
    c.g = gslice; c.s = sreg; c.lane = lane;
    c.sb = (unsigned)__cvta_generic_to_shared(sreg);
    asm volatile("cp.async.ca.shared.global [%0], [%1], 16;"
                 :: "r"(c.sb + lane * 16), "l"(c.g + lane * 4));
    asm volatile("cp.async.ca.shared.global [%0], [%1], 16;"
                 :: "r"(c.sb + 512 + lane * 16), "l"(c.g + 128 + lane * 4));
    asm volatile("cp.async.commit_group;");
    asm volatile("cp.async.ca.shared.global [%0], [%1], 16;"
                 :: "r"(c.sb + 1024 + lane * 16), "l"(c.g + 256 + lane * 4));
    asm volatile("cp.async.ca.shared.global [%0], [%1], 16;"
                 :: "r"(c.sb + 1536 + lane * 16), "l"(c.g + 384 + lane * 4));
    asm volatile("cp.async.commit_group;");
    c.g += 512;
    asm volatile("cp.async.wait_group 1;");
    __syncwarp();
    c.idx = 0; c.phase = 0;
}

__device__ __forceinline__ const float* wc_row(const WCur& c) {
    return c.s + c.phase * 256 + c.idx * 16;
}

__device__ __forceinline__ void wc_adv(WCur& c) {
    if (++c.idx == 16) {
        // refill the buffer just consumed with chunk n+2
        asm volatile("cp.async.ca.shared.global [%0], [%1], 16;"
                     :: "r"(c.sb + c.phase * 1024 + c.lane * 16), "l"(c.g + c.lane * 4));
        asm volatile("cp.async.ca.shared.global [%0], [%1], 16;"
                     :: "r"(c.sb + c.phase * 1024 + 512 + c.lane * 16), "l"(c.g + 128 + c.lane * 4));
        asm volatile("cp.async.commit_group;");
        c.g += 256;
        asm volatile("cp.async.wait_group 1;");   // chunk n+1 ready
        __syncwarp();
        c.phase ^= 1; c.idx = 0;
    }
}

// 8-column accumulate: acc[c] = (row0, row1) packed; weights duplicated (w,w).
// 8 fma2 total, no splits.
__device__ __forceinline__ void acc8(ull f, const float* __restrict__ wr, ull* a) {
    ulonglong2 w01 = *reinterpret_cast<const ulonglong2*>(wr);
    ulonglong2 w23 = *reinterpret_cast<const ulonglong2*>(wr + 4);
    ulonglong2 w45 = *reinterpret_cast<const ulonglong2*>(wr + 8);
    ulonglong2 w67 = *reinterpret_cast<const ulonglong2*>(wr + 12);
    a[0] = fma2(w01.x, f, a[0]); a[1] = fma2(w01.y, f, a[1]);
    a[2] = fma2(w23.x, f, a[2]); a[3] = fma2(w23.y, f, a[3]);
    a[4] = fma2(w45.x, f, a[4]); a[5] = fma2(w45.y, f, a[5]);
    a[6] = fma2(w67.x, f, a[6]); a[7] = fma2(w67.y, f, a[7]);
}

// Symmetric path, triangular u<=v. D==1: CG folded into G at prep.
template <int D, int D3, int M>
__device__ __forceinline__ void tri(const float* __restrict__ xb,
                                    const float* __restrict__ C, int k,
                                    WCur& wc, ull* acc) {
    for (int u = 0; u < M; ++u) {
        ull c[D];
        if (D == 1) {
            c[0] = ld2(xb + u * 64);
        } else {
#pragma unroll
            for (int j = 0; j < D; ++j) {
                ull s = mul2(bc2(C[j * D3 + k]), ld2(xb + (u * D) * 64));
#pragma unroll
                for (int i = 1; i < D; ++i)
                    s = fma2(bc2(C[(i * D + j) * D3 + k]), ld2(xb + (u * D + i) * 64), s);
                c[j] = s;
            }
        }
        for (int v = u; v < M; ++v) {
            ull f = mul2(c[0], ld2(xb + (v * D) * 64));
#pragma unroll
            for (int j = 1; j < D; ++j)
                f = fma2(c[j], ld2(xb + (v * D + j) * 64), f);
            acc8(f, wc_row(wc), acc);
            wc_adv(wc);
        }
    }
}

// Rectangular merged path: inner = DI side, outer = DO side (CG hoisted).
template <int DI, int DO, int D3, int MI, int MO_>
__device__ __forceinline__ void rect(const float* __restrict__ xi,
                                     const float* __restrict__ xo,
                                     const float* __restrict__ C, int k,
                                     WCur& wc, ull* acc) {
    for (int v = 0; v < MO_; ++v) {
        ull g[DI];
#pragma unroll
        for (int i = 0; i < DI; ++i) {
            ull s = mul2(bc2(C[(i * DO) * D3 + k]), ld2(xo + (v * DO) * 64));
#pragma unroll
            for (int j = 1; j < DO; ++j)
                s = fma2(bc2(C[(i * DO + j) * D3 + k]), ld2(xo + (v * DO + j) * 64), s);
            g[i] = s;
        }
        for (int u = 0; u < MI; ++u) {
            ull f = mul2(g[0], ld2(xi + (u * DI) * 64));
#pragma unroll
            for (int i = 1; i < DI; ++i)
                f = fma2(g[i], ld2(xi + (u * DI + i) * 64), f);
            acc8(f, wc_row(wc), acc);
            wc_adv(wc);
        }
    }
}

// ---------------------------------------------------------------- main ------
__global__ __launch_bounds__(480, 2)
void tsq_main(const float* __restrict__ x, float* __restrict__ y, int rows, CGPack cg) {
    extern __shared__ float xs[];   // [240 feat][64 rows] + 15 x 512 weight stage
    const int tid = threadIdx.x;
    const int rowbase = blockIdx.x * 64;
    int nr = rows - rowbase; if (nr > 64) nr = 64;

    for (int i = tid; i < 240 * 64; i += 480) {
        int r = i & 63, f = i >> 6;
        xs[i] = (r < nr) ? x[(size_t)(rowbase + r) * 240 + f] : 0.f;
    }
    __syncthreads();

    const int wid = tid >> 5;
    const int lane = tid & 31;
    const int lane2 = lane << 1;                 // rows (lane2, lane2+1)
    const float* x0b = xs + lane2;               // l=0: feat 0..63
    const float* x1b = xs + 64 * 64 + lane2;     // l=1: feat 64..159
    const float* x2b = xs + 160 * 64 + lane2;    // l=2: feat 160..239
    float* wstage = xs + 15360 + wid * 512;      // warp-private 2KB stage

    // balanced pairing: heavy irrep0 with light irrep2; irrep1 together
    const int u0 = (wid < 8) ? wid : (wid < 14 ? 8 + 2 * (wid - 8) : 28);
    const int u1 = (wid < 8) ? 20 + wid : (wid < 14 ? 9 + 2 * (wid - 8) : 29);

#pragma unroll
    for (int t = 0; t < 2; ++t) {
        const int unit = t ? u1 : u0;
        ull acc[8] = {0ull, 0ull, 0ull, 0ull, 0ull, 0ull, 0ull, 0ull};
        int k = 0, wo = 0;
        WCur wc;
        if (unit < 8) {                          // out irrep 0 (64x0e)
            wo = unit * 8;
            wc_init(wc, g_G0 + unit * (NF0 * 16), wstage, lane);
            tri<1, 1, 64>(x0b, cg.c + O000, 0, wc, acc);
            tri<3, 1, 32>(x1b, cg.c + O110, 0, wc, acc);
            tri<5, 1, 16>(x2b, cg.c + O220, 0, wc, acc);
        } else if (unit < 20) {                  // out irrep 1 (32x1o)
            int q = unit - 8; k = q >> 2; wo = (q & 3) * 8;
            wc_init(wc, g_G1 + (q & 3) * (NF1 * 16), wstage, lane);
            rect<1, 3, 3, 64, 32>(x0b, x1b, cg.c + O011, k, wc, acc);
            rect<3, 5, 3, 32, 16>(x1b, x2b, cg.c + O121, k, wc, acc);
        } else {                                 // out irrep 2 (16x2e)
            int q = unit - 20; k = q >> 1; wo = (q & 1) * 8;
            wc_init(wc, g_G2 + (q & 1) * (NF2 * 16), wstage, lane);
            rect<1, 5, 5, 64, 16>(x0b, x2b, cg.c + O022, k, wc, acc);
            tri<3, 5, 32>(x1b, cg.c + O112, k, wc, acc);
            tri<5, 5, 16>(x2b, cg.c + O222, k, wc, acc);
        }

        float out0[8], out1[8];
#pragma unroll
        for (int p = 0; p < 8; ++p) {
            unsigned lo, hi;
            asm("mov.b64 {%0, %1}, %2;" : "=r"(lo), "=r"(hi) : "l"(acc[p]));
            out0[p] = __uint_as_float(lo);
            out1[p] = __uint_as_float(hi);
        }
        const int r0 = lane2, r1 = lane2 + 1;
        float* y0 = y + (size_t)(rowbase + r0) * 240;
        float* y1 = y + (size_t)(rowbase + r1) * 240;
#pragma unroll
        for (int p = 0; p < 8; ++p) {
            int col = (unit < 8) ? (wo + p)
                    : (unit < 20) ? (64 + (wo + p) * 3 + k)
                                  : (160 + (wo + p) * 5 + k);
            if (r0 < nr) y0[col] = out0[p];
            if (r1 < nr) y1[col] = out1[p];
        }
    }
}

// ---------------------------------------------------------------- launch ----
extern "C" void kernel_launch(void* const* d_in, const int* in_sizes, int n_in,
                              void* d_out, int out_size) {
    (void)n_in; (void)out_size;
    const float* x = (const float*)d_in[0];
    const float* W[11];
    for (int i = 0; i < 11; ++i) W[i] = (const float*)d_in[1 + i];
    int rows = in_sizes[0] / 240;

    CGPack cg;
    build_cg(cg);

    const int ntot = NG0 + NG1 + NG2;
    prep_all<<<(ntot + 255) / 256, 256>>>(W[0], W[1], W[2], W[3], W[4], W[5],
                                          W[6], W[7], W[8], W[9], W[10],
                                          cg.c[O000]);

    const int smem = (15360 + 15 * 512) * sizeof(float);   // 92160 B
    cudaFuncSetAttribute(tsq_main, cudaFuncAttributeMaxDynamicSharedMemorySize, smem);
    int nblk = (rows + 63) / 64;
    tsq_main<<<nblk, 480, smem>>>(x, (float*)d_out, rows, cg);
}

// round 16
// speedup vs baseline: 1.2500x; 1.2500x over previous
#include <cuda_runtime.h>
#include <math.h>
#include <complex>

typedef unsigned long long ull;

// ---------------------------------------------------------------- host CG ---
struct CGPack { float c[363]; };
#define O000 0
#define O011 1
#define O022 10
#define O101 35
#define O110 44
#define O112 53
#define O121 98
#define O202 143
#define O211 168
#define O220 213
#define O222 238

static double fct(int n) { double r = 1.0; for (int i = 2; i <= n; ++i) r *= i; return r; }

static double su2cg(int j1, int m1, int j2, int m2, int j3, int m3) {
    if (m3 != m1 + m2) return 0.0;
    int vmin = -j1 + j2 + m3; if (-j1 + m1 > vmin) vmin = -j1 + m1; if (0 > vmin) vmin = 0;
    int vmax = j2 + j3 + m1; if (j3 - j1 + j2 < vmax) vmax = j3 - j1 + j2; if (j3 + m3 < vmax) vmax = j3 + m3;
    if (vmax < vmin) return 0.0;
    double C = sqrt((2 * j3 + 1) * fct(j3 + j1 - j2) * fct(j3 - j1 + j2) * fct(j1 + j2 - j3)
                    * fct(j3 + m3) * fct(j3 - m3)
                    / (fct(j1 + j2 + j3 + 1) * fct(j1 - m1) * fct(j1 + m1) * fct(j2 - m2) * fct(j2 + m2)));
    double S = 0.0;
    for (int v = vmin; v <= vmax; ++v) {
        double sgn = ((v + j2 + m2) & 1) ? -1.0 : 1.0;
        S += sgn * fct(j2 + j3 + m1 - v) * fct(j1 - m1 + v)
             / (fct(v) * fct(j3 - j1 + j2 - v) * fct(j3 + m3 - v) * fct(v + j1 - j2 - m3));
    }
    return C * S;
}

typedef std::complex<double> cplx;

static void qmat(int l, cplx* q) {
    int n = 2 * l + 1;
    for (int i = 0; i < n * n; ++i) q[i] = 0.0;
    const double is2 = 1.0 / sqrt(2.0);
    for (int m = -l; m < 0; ++m) {
        q[(l + m) * n + (l - m)] = is2;
        q[(l + m) * n + (l + m)] = cplx(0.0, -is2);
    }
    q[l * n + l] = 1.0;
    for (int m = 1; m <= l; ++m) {
        double s = (m & 1) ? -1.0 : 1.0;
        q[(l + m) * n + (l + m)] = s * is2;
        q[(l + m) * n + (l - m)] = cplx(0.0, s * is2);
    }
    cplx ph = 1.0; for (int i = 0; i < l; ++i) ph *= cplx(0.0, -1.0);
    for (int i = 0; i < n * n; ++i) q[i] *= ph;
}

static void real_cg(int l1, int l2, int l3, float* out, double scale) {
    int n1 = 2 * l1 + 1, n2 = 2 * l2 + 1, n3 = 2 * l3 + 1;
    cplx Q1[25], Q2[25], Q3[25];
    qmat(l1, Q1); qmat(l2, Q2); qmat(l3, Q3);
    for (int j = 0; j < n1; ++j)
        for (int lc = 0; lc < n2; ++lc)
            for (int mm = 0; mm < n3; ++mm) {
                cplx s = 0.0;
                for (int i = 0; i < n1; ++i)
                    for (int kk = 0; kk < n2; ++kk) {
                        int m1 = i - l1, m2 = kk - l2, m3 = m1 + m2;
                        if (m3 < -l3 || m3 > l3) continue;
                        double cg = su2cg(l1, m1, l2, m2, l3, m3);
                        if (cg == 0.0) continue;
                        s += Q1[i * n1 + j] * Q2[kk * n2 + lc] * std::conj(Q3[(l3 + m3) * n3 + mm]) * cg;
                    }
                out[(j * n2 + lc) * n3 + mm] = (float)(s.real() * scale);
            }
}

static void build_cg(CGPack& cg) {
    double fan0 = 64.0 * 64 + 32.0 * 32 + 16.0 * 16;
    double fan1 = 64.0 * 32 + 32.0 * 64 + 32.0 * 16 + 16.0 * 32;
    double fan2 = 64.0 * 16 + 16.0 * 64 + 32.0 * 32 + 16.0 * 16;
    double s0 = 1.0 / sqrt(fan0);
    double s1 = sqrt(3.0) / sqrt(fan1);
    double s2 = sqrt(5.0) / sqrt(fan2);
    real_cg(0, 0, 0, cg.c + O000, s0);
    real_cg(0, 1, 1, cg.c + O011, s1);
    real_cg(0, 2, 2, cg.c + O022, s2);
    real_cg(1, 0, 1, cg.c + O101, s1);
    real_cg(1, 1, 0, cg.c + O110, s0);
    real_cg(1, 1, 2, cg.c + O112, s2);
    real_cg(1, 2, 1, cg.c + O121, s1);
    real_cg(2, 0, 2, cg.c + O202, s2);
    real_cg(2, 1, 1, cg.c + O211, s1);
    real_cg(2, 2, 0, cg.c + O220, s0);
    real_cg(2, 2, 2, cg.c + O222, s2);
}

// --------------------------------------------------- packed merged weights --
// Slice-major layout: G[slice][feature][8]. Each 8-col unit streams a fully
// contiguous region. +512 floats pad: cp.async prefetch overruns <= 1KB.
#define NF0 2744
#define NF1 2560
#define NF2 1688
#define NG0 (NF0 * 64)
#define NG1 (NF1 * 32)
#define NG2 (NF2 * 16)
__device__ __align__(16) float g_G0[NG0 + 512];
__device__ __align__(16) float g_G1[NG1 + 512];
__device__ __align__(16) float g_G2[NG2 + 512];

__global__ void prep_all(const float* __restrict__ W0, const float* __restrict__ W1,
                         const float* __restrict__ W2, const float* __restrict__ W3,
                         const float* __restrict__ W4, const float* __restrict__ W5,
                         const float* __restrict__ W6, const float* __restrict__ W7,
                         const float* __restrict__ W8, const float* __restrict__ W9,
                         const float* __restrict__ W10, float c000) {
    int i = blockIdx.x * blockDim.x + threadIdx.x;
    if (i < NG0) {
        int f = i >> 6, w = i & 63;
        float val;
        if (f < 2080) {
            int t = f, u = 0; while (t >= 64 - u) { t -= 64 - u; ++u; } int v = u + t;
            val = W0[(u * 64 + v) * 64 + w];
            if (v != u) val += W0[(v * 64 + u) * 64 + w];
            val *= c000;   // fold scalar CG of the 0x0->0 path
        } else if (f < 2608) {
            int t = f - 2080, u = 0; while (t >= 32 - u) { t -= 32 - u; ++u; } int v = u + t;
            val = W4[(u * 32 + v) * 64 + w];
            if (v != u) val += W4[(v * 32 + u) * 64 + w];
        } else {
            int t = f - 2608, u = 0; while (t >= 16 - u) { t -= 16 - u; ++u; } int v = u + t;
            val = W9[(u * 16 + v) * 64 + w];
            if (v != u) val += W9[(v * 16 + u) * 64 + w];
        }
        g_G0[(w >> 3) * (NF0 * 8) + f * 8 + (w & 7)] = val;
        return;
    }
    i -= NG0;
    if (i < NG1) {
        int f = i >> 5, w = i & 31;
        float val;
        if (f < 2048) {              // outer v1 (32) x inner u0 (64)
            int v = f >> 6, u = f & 63;
            val = W1[(u * 32 + v) * 32 + w] + W3[(v * 64 + u) * 32 + w];
        } else {                     // outer v2 (16) x inner u1 (32)
            int t = f - 2048; int v = t >> 5, u = t & 31;
            val = W6[(u * 16 + v) * 32 + w] + W8[(v * 32 + u) * 32 + w];
        }
        g_G1[(w >> 3) * (NF1 * 8) + f * 8 + (w & 7)] = val;
        return;
    }
    i -= NG1;
    if (i < NG2) {
        int f = i >> 4, w = i & 15;
        float val;
        if (f < 1024) {              // outer v2 (16) x inner u0 (64)
            int v = f >> 6, u = f & 63;
            val = W2[(u * 16 + v) * 16 + w] + W7[(v * 64 + u) * 16 + w];
        } else if (f < 1552) {
            int t = f - 1024, u = 0; while (t >= 32 - u) { t -= 32 - u; ++u; } int v = u + t;
            val = W5[(u * 32 + v) * 16 + w];
            if (v != u) val += W5[(v * 32 + u) * 16 + w];
        } else {
            int t = f - 1552, u = 0; while (t >= 16 - u) { t -= 16 - u; ++u; } int v = u + t;
            val = W10[(u * 16 + v) * 16 + w];
            if (v != u) val += W10[(v * 16 + u) * 16 + w];
        }
        g_G2[(w >> 3) * (NF2 * 8) + f * 8 + (w & 7)] = val;
    }
}

// -------------------------------------------------------------- f32x2 ops ---
__device__ __forceinline__ ull fma2(ull a, ull b, ull c) {
    ull d; asm("fma.rn.f32x2 %0, %1, %2, %3;" : "=l"(d) : "l"(a), "l"(b), "l"(c)); return d;
}
__device__ __forceinline__ ull mul2(ull a, ull b) {
    ull d; asm("mul.rn.f32x2 %0, %1, %2;" : "=l"(d) : "l"(a), "l"(b)); return d;
}
__device__ __forceinline__ ull bc2(float s) {
    ull d; asm("mov.b64 %0, {%1, %1};" : "=l"(d) : "f"(s)); return d;
}
__device__ __forceinline__ ull ld2(const float* p) { return *reinterpret_cast<const ull*>(p); }

__device__ __forceinline__ void splitbc(ull f, ull& fl, ull& fh) {
    unsigned lo, hi;
    asm("mov.b64 {%0, %1}, %2;" : "=r"(lo), "=r"(hi) : "l"(f));
    asm("mov.b64 %0, {%1, %1};" : "=l"(fl) : "r"(lo));
    asm("mov.b64 %0, {%1, %1};" : "=l"(fh) : "r"(hi));
}

// ----------------------------------------------- cp.async weight cursor -----
// Warp-private double buffer: 2 x 16 features x 32B = 2 x 512B in smem.
// Each lane copies one 16B piece per chunk. Prefetch distance = 16 iterations.
struct WCur {
    const float* g;   // next chunk global ptr
    float*       s;   // generic smem base (256 floats)
    unsigned     sb;  // shared-space byte address of s
    int          idx;
    int          phase;
    int          lane;
};

__device__ __forceinline__ void wc_init(WCur& c, const float* gslice, float* sreg, int lane) {
    c.g = gslice; c.s = sreg; c.lane = lane;
    c.sb = (unsigned)__cvta_generic_to_shared(sreg);
    asm volatile("cp.async.ca.shared.global [%0], [%1], 16;"
                 :: "r"(c.sb + lane * 16), "l"(c.g + lane * 4));
    asm volatile("cp.async.commit_group;");
    asm volatile("cp.async.ca.shared.global [%0], [%1], 16;"
                 :: "r"(c.sb + 512 + lane * 16), "l"(c.g + 128 + lane * 4));
    asm volatile("cp.async.commit_group;");
    c.g += 256;
    asm volatile("cp.async.wait_group 1;");
    __syncwarp();
    c.idx = 0; c.phase = 0;
}

__device__ __forceinline__ const float* wc_row(const WCur& c) {
    return c.s + c.phase * 128 + c.idx * 8;
}

__device__ __forceinline__ void wc_adv(WCur& c) {
    if (++c.idx == 16) {
        // refill the buffer just consumed with chunk n+2
        asm volatile("cp.async.ca.shared.global [%0], [%1], 16;"
                     :: "r"(c.sb + c.phase * 512 + c.lane * 16), "l"(c.g + c.lane * 4));
        asm volatile("cp.async.commit_group;");
        c.g += 128;
        asm volatile("cp.async.wait_group 1;");   // chunk n+1 ready
        __syncwarp();
        c.phase ^= 1; c.idx = 0;
    }
}

// 8-column accumulate from staged smem weights.
__device__ __forceinline__ void acc8(ull f, const float* __restrict__ wr, ull* a) {
    ulonglong2 wa = *reinterpret_cast<const ulonglong2*>(wr);
    ulonglong2 wb = *reinterpret_cast<const ulonglong2*>(wr + 4);
    ull fl, fh; splitbc(f, fl, fh);
    a[0] = fma2(wa.x, fl, a[0]); a[1] = fma2(wa.y, fl, a[1]);
    a[2] = fma2(wb.x, fl, a[2]); a[3] = fma2(wb.y, fl, a[3]);
    a[4] = fma2(wa.x, fh, a[4]); a[5] = fma2(wa.y, fh, a[5]);
    a[6] = fma2(wb.x, fh, a[6]); a[7] = fma2(wb.y, fh, a[7]);
}

// Symmetric path, triangular u<=v. Generic version (D=3,5) reads xs layout.
template <int D, int D3, int M>
__device__ __forceinline__ void tri(const float* __restrict__ xb,
                                    const float* __restrict__ C, int k,
                                    WCur& wc, ull* acc) {
    for (int u = 0; u < M; ++u) {
        ull c[D];
#pragma unroll
        for (int j = 0; j < D; ++j) {
            ull s = mul2(bc2(C[j * D3 + k]), ld2(xb + (u * D) * 64));
#pragma unroll
            for (int i = 1; i < D; ++i)
                s = fma2(bc2(C[(i * D + j) * D3 + k]), ld2(xb + (u * D + i) * 64), s);
            c[j] = s;
        }
        for (int v = u; v < M; ++v) {
            ull f = mul2(c[0], ld2(xb + (v * D) * 64));
#pragma unroll
            for (int j = 1; j < D; ++j)
                f = fma2(c[j], ld2(xb + (v * D + j) * 64), f);
            acc8(f, wc_row(wc), acc);
            wc_adv(wc);
        }
    }
}

// 0(x)0 triangular using the pair-interleaved l=0 copy: two features per
// LDS.128. xpl = xp + lane*4.
__device__ __forceinline__ void tri1p(const float* __restrict__ xpl,
                                      WCur& wc, ull* acc) {
    for (int u = 0; u < 64; ++u) {
        ull c0 = ld2(xpl + (u >> 1) * 128 + (u & 1) * 2);
        int v = u;
        if (v & 1) {                 // odd start: single feature first
            ull f = mul2(c0, ld2(xpl + (v >> 1) * 128 + 2));
            acc8(f, wc_row(wc), acc); wc_adv(wc);
            ++v;
        }
        for (; v < 64; v += 2) {     // features (v, v+1) in one LDS.128
            ulonglong2 xv = *reinterpret_cast<const ulonglong2*>(xpl + (v >> 1) * 128);
            ull f = mul2(c0, xv.x);
            acc8(f, wc_row(wc), acc); wc_adv(wc);
            f = mul2(c0, xv.y);
            acc8(f, wc_row(wc), acc); wc_adv(wc);
        }
    }
}

// Rectangular merged path, inner = l=0 side via pair-interleaved copy.
// Outer DO side CG-hoisted; feature order (v outer, u inner 0..63).
template <int DO, int D3, int MO_>
__device__ __forceinline__ void rect1p(const float* __restrict__ xpl,
                                       const float* __restrict__ xo,
                                       const float* __restrict__ C, int k,
                                       WCur& wc, ull* acc) {
    for (int v = 0; v < MO_; ++v) {
        ull g0 = mul2(bc2(C[k]), ld2(xo + (v * DO) * 64));
#pragma unroll
        for (int j = 1; j < DO; ++j)
            g0 = fma2(bc2(C[j * D3 + k]), ld2(xo + (v * DO + j) * 64), g0);
        for (int u = 0; u < 64; u += 2) {
            ulonglong2 xv = *reinterpret_cast<const ulonglong2*>(xpl + (u >> 1) * 128);
            ull f = mul2(g0, xv.x);
            acc8(f, wc_row(wc), acc); wc_adv(wc);
            f = mul2(g0, xv.y);
            acc8(f, wc_row(wc), acc); wc_adv(wc);
        }
    }
}

// Rectangular merged path (generic): inner = DI side, outer = DO side.
template <int DI, int DO, int D3, int MI, int MO_>
__device__ __forceinline__ void rect(const float* __restrict__ xi,
                                     const float* __restrict__ xo,
                                     const float* __restrict__ C, int k,
                                     WCur& wc, ull* acc) {
    for (int v = 0; v < MO_; ++v) {
        ull g[DI];
#pragma unroll
        for (int i = 0; i < DI; ++i) {
            ull s = mul2(bc2(C[(i * DO) * D3 + k]), ld2(xo + (v * DO) * 64));
#pragma unroll
            for (int j = 1; j < DO; ++j)
                s = fma2(bc2(C[(i * DO + j) * D3 + k]), ld2(xo + (v * DO + j) * 64), s);
            g[i] = s;
        }
        for (int u = 0; u < MI; ++u) {
            ull f = mul2(g[0], ld2(xi + (u * DI) * 64));
#pragma unroll
            for (int i = 1; i < DI; ++i)
                f = fma2(g[i], ld2(xi + (u * DI + i) * 64), f);
            acc8(f, wc_row(wc), acc);
            wc_adv(wc);
        }
    }
}

// ---------------------------------------------------------------- main ------
// smem layout (floats):
//   [0, 15360)        xs: [240 feat][64 rows]
//   [15360, 19456)    xp: pair-interleaved l=0 copy [32 f-pairs][32 rowpairs][4]
//   [19456, +15*256)  per-warp weight stages (1KB each)
__global__ __launch_bounds__(480, 2)
void tsq_main(const float* __restrict__ x, float* __restrict__ y, int rows, CGPack cg) {
    extern __shared__ float xs[];
    float* xp = xs + 15360;
    const int tid = threadIdx.x;
    const int rowbase = blockIdx.x * 64;
    int nr = rows - rowbase; if (nr > 64) nr = 64;

    for (int i = tid; i < 240 * 64; i += 480) {
        int r = i & 63, f = i >> 6;
        float val = (r < nr) ? x[(size_t)(rowbase + r) * 240 + f] : 0.f;
        xs[i] = val;
        if (f < 64)
            xp[(f >> 1) * 128 + (r >> 1) * 4 + ((f & 1) << 1) + (r & 1)] = val;
    }
    __syncthreads();

    const int wid = tid >> 5;
    const int lane = tid & 31;
    const int lane2 = lane << 1;                 // rows (lane2, lane2+1)
    const float* x0b = xs + lane2;               // l=0: feat 0..63
    const float* x1b = xs + 64 * 64 + lane2;     // l=1: feat 64..159
    const float* x2b = xs + 160 * 64 + lane2;    // l=2: feat 160..239
    const float* xpl = xp + lane * 4;            // this lane's rowpair package
    float* wstage = xs + 19456 + wid * 256;      // warp-private 1KB stage
    (void)x0b;

    // balanced pairing: heavy irrep0 with light irrep2; irrep1 together
    const int u0 = (wid < 8) ? wid : (wid < 14 ? 8 + 2 * (wid - 8) : 28);
    const int u1 = (wid < 8) ? 20 + wid : (wid < 14 ? 9 + 2 * (wid - 8) : 29);

#pragma unroll
    for (int t = 0; t < 2; ++t) {
        const int unit = t ? u1 : u0;
        ull acc[8] = {0ull, 0ull, 0ull, 0ull, 0ull, 0ull, 0ull, 0ull};
        int k = 0, wo = 0;
        WCur wc;
        if (unit < 8) {                          // out irrep 0 (64x0e)
            wo = unit * 8;
            wc_init(wc, g_G0 + unit * (NF0 * 8), wstage, lane);
            tri1p(xpl, wc, acc);
            tri<3, 1, 32>(x1b, cg.c + O110, 0, wc, acc);
            tri<5, 1, 16>(x2b, cg.c + O220, 0, wc, acc);
        } else if (unit < 20) {                  // out irrep 1 (32x1o)
            int q = unit - 8; k = q >> 2; wo = (q & 3) * 8;
            wc_init(wc, g_G1 + (q & 3) * (NF1 * 8), wstage, lane);
            rect1p<3, 3, 32>(xpl, x1b, cg.c + O011, k, wc, acc);
            rect<3, 5, 3, 32, 16>(x1b, x2b, cg.c + O121, k, wc, acc);
        } else {                                 // out irrep 2 (16x2e)
            int q = unit - 20; k = q >> 1; wo = (q & 1) * 8;
            wc_init(wc, g_G2 + (q & 1) * (NF2 * 8), wstage, lane);
            rect1p<5, 5, 16>(xpl, x2b, cg.c + O022, k, wc, acc);
            tri<3, 5, 32>(x1b, cg.c + O112, k, wc, acc);
            tri<5, 5, 16>(x2b, cg.c + O222, k, wc, acc);
        }

        float out0[8], out1[8];
#pragma unroll
        for (int p = 0; p < 4; ++p) {
            unsigned lo, hi;
            asm("mov.b64 {%0, %1}, %2;" : "=r"(lo), "=r"(hi) : "l"(acc[p]));
            out0[2 * p] = __uint_as_float(lo); out0[2 * p + 1] = __uint_as_float(hi);
            asm("mov.b64 {%0, %1}, %2;" : "=r"(lo), "=r"(hi) : "l"(acc[p + 4]));
            out1[2 * p] = __uint_as_float(lo); out1[2 * p + 1] = __uint_as_float(hi);
        }
        const int r0 = lane2, r1 = lane2 + 1;
        float* y0 = y + (size_t)(rowbase + r0) * 240;
        float* y1 = y + (size_t)(rowbase + r1) * 240;
#pragma unroll
        for (int p = 0; p < 8; ++p) {
            int col = (unit < 8) ? (wo + p)
                    : (unit < 20) ? (64 + (wo + p) * 3 + k)
                                  : (160 + (wo + p) * 5 + k);
            if (r0 < nr) y0[col] = out0[p];
            if (r1 < nr) y1[col] = out1[p];
        }
    }
}

// ---------------------------------------------------------------- launch ----
extern "C" void kernel_launch(void* const* d_in, const int* in_sizes, int n_in,
                              void* d_out, int out_size) {
    (void)n_in; (void)out_size;
    const float* x = (const float*)d_in[0];
    const float* W[11];
    for (int i = 0; i < 11; ++i) W[i] = (const float*)d_in[1 + i];
    int rows = in_sizes[0] / 240;

    CGPack cg;
    build_cg(cg);

    const int ntot = NG0 + NG1 + NG2;
    prep_all<<<(ntot + 255) / 256, 256>>>(W[0], W[1], W[2], W[3], W[4], W[5],
                                          W[6], W[7], W[8], W[9], W[10],
                                          cg.c[O000]);

    const int smem = (19456 + 15 * 256) * sizeof(float);   // 93184 B
    cudaFuncSetAttribute(tsq_main, cudaFuncAttributeMaxDynamicSharedMemorySize, smem);
    int nblk = (rows + 63) / 64;
    tsq_main<<<nblk, 480, smem>>>(x, (float*)d_out, rows, cg);
}

// round 17
// speedup vs baseline: 1.3643x; 1.0915x over previous
#include <cuda_runtime.h>
#include <math.h>
#include <complex>

typedef unsigned long long ull;

// ---------------------------------------------------------------- host CG ---
struct CGPack { float c[363]; };
#define O000 0
#define O011 1
#define O022 10
#define O101 35
#define O110 44
#define O112 53
#define O121 98
#define O202 143
#define O211 168
#define O220 213
#define O222 238

static double fct(int n) { double r = 1.0; for (int i = 2; i <= n; ++i) r *= i; return r; }

static double su2cg(int j1, int m1, int j2, int m2, int j3, int m3) {
    if (m3 != m1 + m2) return 0.0;
    int vmin = -j1 + j2 + m3; if (-j1 + m1 > vmin) vmin = -j1 + m1; if (0 > vmin) vmin = 0;
    int vmax = j2 + j3 + m1; if (j3 - j1 + j2 < vmax) vmax = j3 - j1 + j2; if (j3 + m3 < vmax) vmax = j3 + m3;
    if (vmax < vmin) return 0.0;
    double C = sqrt((2 * j3 + 1) * fct(j3 + j1 - j2) * fct(j3 - j1 + j2) * fct(j1 + j2 - j3)
                    * fct(j3 + m3) * fct(j3 - m3)
                    / (fct(j1 + j2 + j3 + 1) * fct(j1 - m1) * fct(j1 + m1) * fct(j2 - m2) * fct(j2 + m2)));
    double S = 0.0;
    for (int v = vmin; v <= vmax; ++v) {
        double sgn = ((v + j2 + m2) & 1) ? -1.0 : 1.0;
        S += sgn * fct(j2 + j3 + m1 - v) * fct(j1 - m1 + v)
             / (fct(v) * fct(j3 - j1 + j2 - v) * fct(j3 + m3 - v) * fct(v + j1 - j2 - m3));
    }
    return C * S;
}

typedef std::complex<double> cplx;

static void qmat(int l, cplx* q) {
    int n = 2 * l + 1;
    for (int i = 0; i < n * n; ++i) q[i] = 0.0;
    const double is2 = 1.0 / sqrt(2.0);
    for (int m = -l; m < 0; ++m) {
        q[(l + m) * n + (l - m)] = is2;
        q[(l + m) * n + (l + m)] = cplx(0.0, -is2);
    }
    q[l * n + l] = 1.0;
    for (int m = 1; m <= l; ++m) {
        double s = (m & 1) ? -1.0 : 1.0;
        q[(l + m) * n + (l + m)] = s * is2;
        q[(l + m) * n + (l - m)] = cplx(0.0, s * is2);
    }
    cplx ph = 1.0; for (int i = 0; i < l; ++i) ph *= cplx(0.0, -1.0);
    for (int i = 0; i < n * n; ++i) q[i] *= ph;
}

static void real_cg(int l1, int l2, int l3, float* out, double scale) {
    int n1 = 2 * l1 + 1, n2 = 2 * l2 + 1, n3 = 2 * l3 + 1;
    cplx Q1[25], Q2[25], Q3[25];
    qmat(l1, Q1); qmat(l2, Q2); qmat(l3, Q3);
    for (int j = 0; j < n1; ++j)
        for (int lc = 0; lc < n2; ++lc)
            for (int mm = 0; mm < n3; ++mm) {
                cplx s = 0.0;
                for (int i = 0; i < n1; ++i)
                    for (int kk = 0; kk < n2; ++kk) {
                        int m1 = i - l1, m2 = kk - l2, m3 = m1 + m2;
                        if (m3 < -l3 || m3 > l3) continue;
                        double cg = su2cg(l1, m1, l2, m2, l3, m3);
                        if (cg == 0.0) continue;
                        s += Q1[i * n1 + j] * Q2[kk * n2 + lc] * std::conj(Q3[(l3 + m3) * n3 + mm]) * cg;
                    }
                out[(j * n2 + lc) * n3 + mm] = (float)(s.real() * scale);
            }
}

static void build_cg(CGPack& cg) {
    double fan0 = 64.0 * 64 + 32.0 * 32 + 16.0 * 16;
    double fan1 = 64.0 * 32 + 32.0 * 64 + 32.0 * 16 + 16.0 * 32;
    double fan2 = 64.0 * 16 + 16.0 * 64 + 32.0 * 32 + 16.0 * 16;
    double s0 = 1.0 / sqrt(fan0);
    double s1 = sqrt(3.0) / sqrt(fan1);
    double s2 = sqrt(5.0) / sqrt(fan2);
    real_cg(0, 0, 0, cg.c + O000, s0);
    real_cg(0, 1, 1, cg.c + O011, s1);
    real_cg(0, 2, 2, cg.c + O022, s2);
    real_cg(1, 0, 1, cg.c + O101, s1);
    real_cg(1, 1, 0, cg.c + O110, s0);
    real_cg(1, 1, 2, cg.c + O112, s2);
    real_cg(1, 2, 1, cg.c + O121, s1);
    real_cg(2, 0, 2, cg.c + O202, s2);
    real_cg(2, 1, 1, cg.c + O211, s1);
    real_cg(2, 2, 0, cg.c + O220, s0);
    real_cg(2, 2, 2, cg.c + O222, s2);
}

// --------------------------------------------------- packed merged weights --
// Slice-major layout: G[slice][feature][8]. Each 8-col unit streams a fully
// contiguous region. +512 floats pad: cp.async prefetch overruns <= 1KB.
#define NF0 2744
#define NF1 2560
#define NF2 1688
#define NG0 (NF0 * 64)
#define NG1 (NF1 * 32)
#define NG2 (NF2 * 16)
__device__ __align__(16) float g_G0[NG0 + 512];
__device__ __align__(16) float g_G1[NG1 + 512];
__device__ __align__(16) float g_G2[NG2 + 512];

__global__ void prep_all(const float* __restrict__ W0, const float* __restrict__ W1,
                         const float* __restrict__ W2, const float* __restrict__ W3,
                         const float* __restrict__ W4, const float* __restrict__ W5,
                         const float* __restrict__ W6, const float* __restrict__ W7,
                         const float* __restrict__ W8, const float* __restrict__ W9,
                         const float* __restrict__ W10, float c000) {
    int i = blockIdx.x * blockDim.x + threadIdx.x;
    if (i < NG0) {
        int f = i >> 6, w = i & 63;
        float val;
        if (f < 2080) {
            int t = f, u = 0; while (t >= 64 - u) { t -= 64 - u; ++u; } int v = u + t;
            val = W0[(u * 64 + v) * 64 + w];
            if (v != u) val += W0[(v * 64 + u) * 64 + w];
            val *= c000;   // fold scalar CG of the 0x0->0 path
        } else if (f < 2608) {
            int t = f - 2080, u = 0; while (t >= 32 - u) { t -= 32 - u; ++u; } int v = u + t;
            val = W4[(u * 32 + v) * 64 + w];
            if (v != u) val += W4[(v * 32 + u) * 64 + w];
        } else {
            int t = f - 2608, u = 0; while (t >= 16 - u) { t -= 16 - u; ++u; } int v = u + t;
            val = W9[(u * 16 + v) * 64 + w];
            if (v != u) val += W9[(v * 16 + u) * 64 + w];
        }
        g_G0[(w >> 3) * (NF0 * 8) + f * 8 + (w & 7)] = val;
        return;
    }
    i -= NG0;
    if (i < NG1) {
        int f = i >> 5, w = i & 31;
        float val;
        if (f < 2048) {              // outer v1 (32) x inner u0 (64)
            int v = f >> 6, u = f & 63;
            val = W1[(u * 32 + v) * 32 + w] + W3[(v * 64 + u) * 32 + w];
        } else {                     // outer v2 (16) x inner u1 (32)
            int t = f - 2048; int v = t >> 5, u = t & 31;
            val = W6[(u * 16 + v) * 32 + w] + W8[(v * 32 + u) * 32 + w];
        }
        g_G1[(w >> 3) * (NF1 * 8) + f * 8 + (w & 7)] = val;
        return;
    }
    i -= NG1;
    if (i < NG2) {
        int f = i >> 4, w = i & 15;
        float val;
        if (f < 1024) {              // outer v2 (16) x inner u0 (64)
            int v = f >> 6, u = f & 63;
            val = W2[(u * 16 + v) * 16 + w] + W7[(v * 64 + u) * 16 + w];
        } else if (f < 1552) {
            int t = f - 1024, u = 0; while (t >= 32 - u) { t -= 32 - u; ++u; } int v = u + t;
            val = W5[(u * 32 + v) * 16 + w];
            if (v != u) val += W5[(v * 32 + u) * 16 + w];
        } else {
            int t = f - 1552, u = 0; while (t >= 16 - u) { t -= 16 - u; ++u; } int v = u + t;
            val = W10[(u * 16 + v) * 16 + w];
            if (v != u) val += W10[(v * 16 + u) * 16 + w];
        }
        g_G2[(w >> 3) * (NF2 * 8) + f * 8 + (w & 7)] = val;
    }
}

// -------------------------------------------------------------- f32x2 ops ---
__device__ __forceinline__ ull fma2(ull a, ull b, ull c) {
    ull d; asm("fma.rn.f32x2 %0, %1, %2, %3;" : "=l"(d) : "l"(a), "l"(b), "l"(c)); return d;
}
__device__ __forceinline__ ull mul2(ull a, ull b) {
    ull d; asm("mul.rn.f32x2 %0, %1, %2;" : "=l"(d) : "l"(a), "l"(b)); return d;
}
__device__ __forceinline__ ull bc2(float s) {
    ull d; asm("mov.b64 %0, {%1, %1};" : "=l"(d) : "f"(s)); return d;
}
__device__ __forceinline__ ull ld2(const float* p) { return *reinterpret_cast<const ull*>(p); }

__device__ __forceinline__ void splitbc(ull f, ull& fl, ull& fh) {
    unsigned lo, hi;
    asm("mov.b64 {%0, %1}, %2;" : "=r"(lo), "=r"(hi) : "l"(f));
    asm("mov.b64 %0, {%1, %1};" : "=l"(fl) : "r"(lo));
    asm("mov.b64 %0, {%1, %1};" : "=l"(fh) : "r"(hi));
}

// ----------------------------------------------- cp.async weight cursor -----
// Warp-private double buffer: 2 x 16 features x 32B = 2 x 512B in smem.
// Running read pointer + countdown: no per-feature address recomputation.
struct WCur {
    const float* g;   // next chunk global ptr
    const float* wr;  // current weight-row read ptr (generic)
    float*       s;   // generic smem base (256 floats)
    unsigned     sb;  // shared-space byte address of s
    int          cnt; // features left in current buffer
    int          phase;
    int          lane;
};

__device__ __forceinline__ void wc_init(WCur& c, const float* gslice, float* sreg, int lane) {
    c.g = gslice; c.s = sreg; c.lane = lane;
    c.sb = (unsigned)__cvta_generic_to_shared(sreg);
    asm volatile("cp.async.ca.shared.global [%0], [%1], 16;"
                 :: "r"(c.sb + lane * 16), "l"(c.g + lane * 4));
    asm volatile("cp.async.commit_group;");
    asm volatile("cp.async.ca.shared.global [%0], [%1], 16;"
                 :: "r"(c.sb + 512 + lane * 16), "l"(c.g + 128 + lane * 4));
    asm volatile("cp.async.commit_group;");
    c.g += 256;
    asm volatile("cp.async.wait_group 1;");
    __syncwarp();
    c.wr = sreg; c.cnt = 16; c.phase = 0;
}

__device__ __forceinline__ void wc_wrap(WCur& c) {
    // refill the buffer just consumed with chunk n+2
    asm volatile("cp.async.ca.shared.global [%0], [%1], 16;"
                 :: "r"(c.sb + c.phase * 512 + c.lane * 16), "l"(c.g + c.lane * 4));
    asm volatile("cp.async.commit_group;");
    c.g += 128;
    asm volatile("cp.async.wait_group 1;");   // chunk n+1 ready
    __syncwarp();
    c.phase ^= 1;
    c.wr = c.s + c.phase * 128;
    c.cnt = 16;
}

__device__ __forceinline__ void wc_adv(WCur& c) {
    c.wr += 8;
    if (--c.cnt == 0) wc_wrap(c);
}

// paired advance: only valid when cnt is even at entry (16-chunk parity held)
__device__ __forceinline__ void wc_adv2(WCur& c) {
    c.wr += 16;
    c.cnt -= 2;
    if (c.cnt == 0) wc_wrap(c);
}

// 8-column accumulate from staged smem weights.
__device__ __forceinline__ void acc8(ull f, const float* __restrict__ wr, ull* a) {
    ulonglong2 wa = *reinterpret_cast<const ulonglong2*>(wr);
    ulonglong2 wb = *reinterpret_cast<const ulonglong2*>(wr + 4);
    ull fl, fh; splitbc(f, fl, fh);
    a[0] = fma2(wa.x, fl, a[0]); a[1] = fma2(wa.y, fl, a[1]);
    a[2] = fma2(wb.x, fl, a[2]); a[3] = fma2(wb.y, fl, a[3]);
    a[4] = fma2(wa.x, fh, a[4]); a[5] = fma2(wa.y, fh, a[5]);
    a[6] = fma2(wb.x, fh, a[6]); a[7] = fma2(wb.y, fh, a[7]);
}

// Symmetric path, triangular u<=v. Generic version (D=3,5) reads xs layout.
template <int D, int D3, int M>
__device__ __forceinline__ void tri(const float* __restrict__ xb,
                                    const float* __restrict__ C, int k,
                                    WCur& wc, ull* acc) {
    for (int u = 0; u < M; ++u) {
        ull c[D];
#pragma unroll
        for (int j = 0; j < D; ++j) {
            ull s = mul2(bc2(C[j * D3 + k]), ld2(xb + (u * D) * 64));
#pragma unroll
            for (int i = 1; i < D; ++i)
                s = fma2(bc2(C[(i * D + j) * D3 + k]), ld2(xb + (u * D + i) * 64), s);
            c[j] = s;
        }
        for (int v = u; v < M; ++v) {
            ull f = mul2(c[0], ld2(xb + (v * D) * 64));
#pragma unroll
            for (int j = 1; j < D; ++j)
                f = fma2(c[j], ld2(xb + (v * D + j) * 64), f);
            acc8(f, wc.wr, acc);
            wc_adv(wc);
        }
    }
}

// 0(x)0 triangular using the pair-interleaved l=0 copy: two features per
// LDS.128. xpl = xp + lane*4.
__device__ __forceinline__ void tri1p(const float* __restrict__ xpl,
                                      WCur& wc, ull* acc) {
    for (int u = 0; u < 64; ++u) {
        ull c0 = ld2(xpl + (u >> 1) * 128 + (u & 1) * 2);
        int v = u;
        if (v & 1) {                 // odd start: single feature first
            ull f = mul2(c0, ld2(xpl + (v >> 1) * 128 + 2));
            acc8(f, wc.wr, acc); wc_adv(wc);
            ++v;
        }
        for (; v < 64; v += 2) {     // features (v, v+1) in one LDS.128
            ulonglong2 xv = *reinterpret_cast<const ulonglong2*>(xpl + (v >> 1) * 128);
            ull f = mul2(c0, xv.x);
            acc8(f, wc.wr, acc);
            ull f2 = mul2(c0, xv.y);
            acc8(f2, wc.wr + 8, acc);
            wc_adv2(wc);             // safe: pairs keep 16-chunk parity? see note
        }
    }
}

// NOTE on tri1p parity: wc_adv2 requires cnt even at entry. Rows of this
// triangle consume (64-u) features; odd-start singles use wc_adv first, so
// each v-pair entry has consumed features ≡ 0 mod 2 within this segment —
// but cnt parity also depends on total consumed so far, which is even at
// segment start (0) and stays even before each pair (singles flip it, then
// pairs preserve it...). Singles make it odd → wc_adv2 could skip cnt==0.
// To keep correctness we fall back to per-feature advance when parity is odd.

// Rectangular merged path, inner = l=0 side via pair-interleaved copy.
// Outer DO side CG-hoisted; feature order (v outer, u inner 0..63).
template <int DO, int D3, int MO_>
__device__ __forceinline__ void rect1p(const float* __restrict__ xpl,
                                       const float* __restrict__ xo,
                                       const float* __restrict__ C, int k,
                                       WCur& wc, ull* acc) {
    for (int v = 0; v < MO_; ++v) {
        ull g0 = mul2(bc2(C[k]), ld2(xo + (v * DO) * 64));
#pragma unroll
        for (int j = 1; j < DO; ++j)
            g0 = fma2(bc2(C[j * D3 + k]), ld2(xo + (v * DO + j) * 64), g0);
        for (int u = 0; u < 64; u += 2) {
            ulonglong2 xv = *reinterpret_cast<const ulonglong2*>(xpl + (u >> 1) * 128);
            ull f = mul2(g0, xv.x);
            acc8(f, wc.wr, acc);
            ull f2 = mul2(g0, xv.y);
            acc8(f2, wc.wr + 8, acc);
            wc_adv2(wc);             // segment consumes 64·MO_ features, starts
                                     // at even cnt → parity preserved
        }
    }
}

// Rectangular merged path (generic): inner = DI side, outer = DO side.
template <int DI, int DO, int D3, int MI, int MO_>
__device__ __forceinline__ void rect(const float* __restrict__ xi,
                                     const float* __restrict__ xo,
                                     const float* __restrict__ C, int k,
                                     WCur& wc, ull* acc) {
    for (int v = 0; v < MO_; ++v) {
        ull g[DI];
#pragma unroll
        for (int i = 0; i < DI; ++i) {
            ull s = mul2(bc2(C[(i * DO) * D3 + k]), ld2(xo + (v * DO) * 64));
#pragma unroll
            for (int j = 1; j < DO; ++j)
                s = fma2(bc2(C[(i * DO + j) * D3 + k]), ld2(xo + (v * DO + j) * 64), s);
            g[i] = s;
        }
        for (int u = 0; u < MI; ++u) {
            ull f = mul2(g[0], ld2(xi + (u * DI) * 64));
#pragma unroll
            for (int i = 1; i < DI; ++i)
                f = fma2(g[i], ld2(xi + (u * DI + i) * 64), f);
            acc8(f, wc.wr, acc);
            wc_adv(wc);
        }
    }
}

// tri1p with correct parity handling: restructured so pairs always see even
// cnt. We process the triangle as: for each u, if (64-u) is odd do one single
// FIRST (parity flips), then pairs. Since cnt parity at u-row start equals
// total-consumed parity, and consumed after row u is sum_{t<=u}(64-t), parity
// alternates irregularly. Safe option: singles use wc_adv; pairs use wc_adv
// twice when parity odd. We track parity in a register.
__device__ __forceinline__ void tri1p_safe(const float* __restrict__ xpl,
                                           WCur& wc, ull* acc) {
    int odd = 0;  // cnt parity: 0 = even (wc_adv2 safe)
    for (int u = 0; u < 64; ++u) {
        ull c0 = ld2(xpl + (u >> 1) * 128 + (u & 1) * 2);
        int v = u;
        if (v & 1) {
            ull f = mul2(c0, ld2(xpl + (v >> 1) * 128 + 2));
            acc8(f, wc.wr, acc); wc_adv(wc);
            odd ^= 1;
            ++v;
        }
        if (!odd) {
            for (; v < 64; v += 2) {
                ulonglong2 xv = *reinterpret_cast<const ulonglong2*>(xpl + (v >> 1) * 128);
                ull f = mul2(c0, xv.x);
                acc8(f, wc.wr, acc);
                ull f2 = mul2(c0, xv.y);
                acc8(f2, wc.wr + 8, acc);
                wc_adv2(wc);
            }
        } else {
            for (; v < 64; v += 2) {
                ulonglong2 xv = *reinterpret_cast<const ulonglong2*>(xpl + (v >> 1) * 128);
                ull f = mul2(c0, xv.x);
                acc8(f, wc.wr, acc); wc_adv(wc);
                ull f2 = mul2(c0, xv.y);
                acc8(f2, wc.wr, acc); wc_adv(wc);
            }
        }
    }
}

// ---------------------------------------------------------------- main ------
// smem layout (floats):
//   [0, 15360)        xs: [240 feat][64 rows]
//   [15360, 19456)    xp: pair-interleaved l=0 copy [32 f-pairs][32 rowpairs][4]
//   [19456, +15*256)  per-warp weight stages (1KB each)
__global__ __launch_bounds__(480, 2)
void tsq_main(const float* __restrict__ x, float* __restrict__ y, int rows, CGPack cg) {
    extern __shared__ float xs[];
    float* xp = xs + 15360;
    const int tid = threadIdx.x;
    const int rowbase = blockIdx.x * 64;
    int nr = rows - rowbase; if (nr > 64) nr = 64;

    for (int i = tid; i < 240 * 64; i += 480) {
        int r = i & 63, f = i >> 6;
        float val = (r < nr) ? x[(size_t)(rowbase + r) * 240 + f] : 0.f;
        xs[i] = val;
        if (f < 64)
            xp[(f >> 1) * 128 + (r >> 1) * 4 + ((f & 1) << 1) + (r & 1)] = val;
    }
    __syncthreads();

    const int wid = tid >> 5;
    const int lane = tid & 31;
    const int lane2 = lane << 1;                 // rows (lane2, lane2+1)
    const float* x1b = xs + 64 * 64 + lane2;     // l=1: feat 64..159
    const float* x2b = xs + 160 * 64 + lane2;    // l=2: feat 160..239
    const float* xpl = xp + lane * 4;            // this lane's rowpair package
    float* wstage = xs + 19456 + wid * 256;      // warp-private 1KB stage

    // balanced pairing: heavy irrep0 with light irrep2; irrep1 together
    const int u0 = (wid < 8) ? wid : (wid < 14 ? 8 + 2 * (wid - 8) : 28);
    const int u1 = (wid < 8) ? 20 + wid : (wid < 14 ? 9 + 2 * (wid - 8) : 29);

#pragma unroll
    for (int t = 0; t < 2; ++t) {
        const int unit = t ? u1 : u0;
        ull acc[8] = {0ull, 0ull, 0ull, 0ull, 0ull, 0ull, 0ull, 0ull};
        int k = 0, wo = 0;
        WCur wc;
        if (unit < 8) {                          // out irrep 0 (64x0e)
            wo = unit * 8;
            wc_init(wc, g_G0 + unit * (NF0 * 8), wstage, lane);
            tri1p_safe(xpl, wc, acc);
            tri<3, 1, 32>(x1b, cg.c + O110, 0, wc, acc);
            tri<5, 1, 16>(x2b, cg.c + O220, 0, wc, acc);
        } else if (unit < 20) {                  // out irrep 1 (32x1o)
            int q = unit - 8; k = q >> 2; wo = (q & 3) * 8;
            wc_init(wc, g_G1 + (q & 3) * (NF1 * 8), wstage, lane);
            rect1p<3, 3, 32>(xpl, x1b, cg.c + O011, k, wc, acc);
            rect<3, 5, 3, 32, 16>(x1b, x2b, cg.c + O121, k, wc, acc);
        } else {                                 // out irrep 2 (16x2e)
            int q = unit - 20; k = q >> 1; wo = (q & 1) * 8;
            wc_init(wc, g_G2 + (q & 1) * (NF2 * 8), wstage, lane);
            rect1p<5, 5, 16>(xpl, x2b, cg.c + O022, k, wc, acc);
            tri<3, 5, 32>(x1b, cg.c + O112, k, wc, acc);
            tri<5, 5, 16>(x2b, cg.c + O222, k, wc, acc);
        }

        float out0[8], out1[8];
#pragma unroll
        for (int p = 0; p < 4; ++p) {
            unsigned lo, hi;
            asm("mov.b64 {%0, %1}, %2;" : "=r"(lo), "=r"(hi) : "l"(acc[p]));
            out0[2 * p] = __uint_as_float(lo); out0[2 * p + 1] = __uint_as_float(hi);
            asm("mov.b64 {%0, %1}, %2;" : "=r"(lo), "=r"(hi) : "l"(acc[p + 4]));
            out1[2 * p] = __uint_as_float(lo); out1[2 * p + 1] = __uint_as_float(hi);
        }
        const int r0 = lane2, r1 = lane2 + 1;
        float* y0 = y + (size_t)(rowbase + r0) * 240;
        float* y1 = y + (size_t)(rowbase + r1) * 240;
#pragma unroll
        for (int p = 0; p < 8; ++p) {
            int col = (unit < 8) ? (wo + p)
                    : (unit < 20) ? (64 + (wo + p) * 3 + k)
                                  : (160 + (wo + p) * 5 + k);
            if (r0 < nr) y0[col] = out0[p];
            if (r1 < nr) y1[col] = out1[p];
        }
    }
}

// ---------------------------------------------------------------- launch ----
extern "C" void kernel_launch(void* const* d_in, const int* in_sizes, int n_in,
                              void* d_out, int out_size) {
    (void)n_in; (void)out_size;
    const float* x = (const float*)d_in[0];
    const float* W[11];
    for (int i = 0; i < 11; ++i) W[i] = (const float*)d_in[1 + i];
    int rows = in_sizes[0] / 240;

    CGPack cg;
    build_cg(cg);

    const int ntot = NG0 + NG1 + NG2;
    prep_all<<<(ntot + 255) / 256, 256>>>(W[0], W[1], W[2], W[3], W[4], W[5],
                                          W[6], W[7], W[8], W[9], W[10],
                                          cg.c[O000]);

    const int smem = (19456 + 15 * 256) * sizeof(float);   // 93184 B
    cudaFuncSetAttribute(tsq_main, cudaFuncAttributeMaxDynamicSharedMemorySize, smem);
    int nblk = (rows + 63) / 64;
    tsq_main<<<nblk, 480, smem>>>(x, (float*)d_out, rows, cg);
}